// round 1
// baseline (speedup 1.0000x reference)
#include <cuda_runtime.h>

// GINENet: 2x GINEConv(F=128) + classifier(40) + log_softmax
// N=100000 nodes, E=1600000 edges, F=128.
//
// Pipeline (A/B = 51.2MB device ping-pong buffers):
//   detect edge_index dtype (int32 vs int64)
//   A = (1+eps1)*x
//   A += scatter_dst( relu(x[src] + a_e*We1 + be1) )          [atomic float4]
//   B = relu(A@W11+b11); A = relu(B@W12+b12)                  [conv1 out, incl. outer relu]
//   B = (1+eps2)*A
//   B += scatter_dst( relu(A[src] + a_e*We2 + be2) )
//   A = relu(B@W21+b21); B = relu(A@W22+b22)
//   out = log_softmax(B@Wl + bl)

#define NODES_MAX 100000
#define FDIM 128

__device__ float g_A[(size_t)NODES_MAX * FDIM];
__device__ float g_B[(size_t)NODES_MAX * FDIM];
__device__ int g_is64;

__device__ __forceinline__ float* bufsel(int s) { return (s == 0) ? g_A : g_B; }

// ---------------------------------------------------------------------------
// Detect whether edge_index is int64 or int32. Reading an int32 array as
// int64 packs two indices per word; the high 32 bits are a random index in
// [0,100000) which is nonzero with prob ~1-1e-5 per value, so 64 consecutive
// "valid int64" reads imply true int64.
// ---------------------------------------------------------------------------
__global__ void k_detect(const long long* __restrict__ ei, int n_nodes) {
    if (threadIdx.x == 0 && blockIdx.x == 0) {
        int ok = 1;
        for (int i = 0; i < 64; ++i) {
            long long v = ei[i];
            if (v < 0 || v >= (long long)n_nodes) { ok = 0; break; }
        }
        g_is64 = ok;
    }
}

// ---------------------------------------------------------------------------
// out = (1 + eps) * in      (float4-vectorized)
// ---------------------------------------------------------------------------
__global__ void k_scale(const float4* __restrict__ ext_in, int in_sel, int out_sel,
                        const float* __restrict__ eps, int n4) {
    int i = blockIdx.x * blockDim.x + threadIdx.x;
    if (i >= n4) return;
    const float4* in = ext_in ? ext_in : (const float4*)bufsel(in_sel);
    float4* out = (float4*)bufsel(out_sel);
    float s = 1.0f + __ldg(eps);
    float4 v = in[i];
    v.x *= s; v.y *= s; v.z *= s; v.w *= s;
    out[i] = v;
}

// ---------------------------------------------------------------------------
// Edge message + scatter-add:
//   h[dst] += relu(x[src] + a_e * We + be)   (one warp per edge, float4/lane)
// ---------------------------------------------------------------------------
__global__ void k_edge(const void* __restrict__ ei, const float* __restrict__ ea,
                       const float4* __restrict__ x_ext, int x_sel, int h_sel,
                       const float4* __restrict__ We4, const float4* __restrict__ be4,
                       int E) {
    long long t = (long long)blockIdx.x * blockDim.x + threadIdx.x;
    int e = (int)(t >> 5);
    int lane = (int)(t & 31);
    if (e >= E) return;

    const float4* x4 = x_ext ? x_ext : (const float4*)bufsel(x_sel);
    float4* h4 = (float4*)bufsel(h_sel);

    long long src, dst;
    if (g_is64) {
        const long long* p = (const long long*)ei;
        src = __ldg(p + e);
        dst = __ldg(p + E + e);
    } else {
        const int* p = (const int*)ei;
        src = (long long)__ldg(p + e);
        dst = (long long)__ldg(p + E + e);
    }
    float a = __ldg(ea + e);
    float4 xv = __ldg(x4 + src * 32 + lane);
    float4 w = __ldg(We4 + lane);
    float4 b = __ldg(be4 + lane);
    float4 m;
    m.x = fmaxf(fmaf(a, w.x, b.x) + xv.x, 0.0f);
    m.y = fmaxf(fmaf(a, w.y, b.y) + xv.y, 0.0f);
    m.z = fmaxf(fmaf(a, w.z, b.z) + xv.z, 0.0f);
    m.w = fmaxf(fmaf(a, w.w, b.w) + xv.w, 0.0f);
    atomicAdd(h4 + dst * 32 + lane, m);   // sm_90+ vector red.global.add.v4.f32
}

// ---------------------------------------------------------------------------
// C = relu(A @ W + bias)   A:[M,128] W:[128,128] C:[M,128]
// 128x128 block tile, 256 threads, 8x8 micro-tile (cols split tc*4 / tc*4+64
// for conflict-free LDS.128), double-buffered over K (BK=8).
// ---------------------------------------------------------------------------
__global__ __launch_bounds__(256, 2) void k_gemm_relu(
    int a_sel, const float* __restrict__ W, const float* __restrict__ bias,
    int c_sel, int M) {
    const float* A = bufsel(a_sel);
    float* C = bufsel(c_sel);

    __shared__ float As[2][8][132];   // [k][m], padded row
    __shared__ float Bs[2][8][132];   // [k][n], padded row

    const int tid = threadIdx.x;
    const int tr = tid >> 4;          // 0..15 -> rows tr*8..tr*8+7
    const int tc = tid & 15;          // 0..15 -> cols tc*4..+3 and tc*4+64..+67
    const int arow = tid >> 1;        // 0..127
    const int acol = (tid & 1) << 2;  // 0 or 4
    const int brow = tid >> 5;        // 0..7
    const int bcol = (tid & 31) << 2; // 0..124
    const int rowBase = blockIdx.x * 128;

    float acc[8][8];
#pragma unroll
    for (int i = 0; i < 8; ++i)
#pragma unroll
        for (int j = 0; j < 8; ++j) acc[i][j] = 0.0f;

    // prologue: stage 0
    {
        int grow = rowBase + arow;
        float4 v = make_float4(0.f, 0.f, 0.f, 0.f);
        if (grow < M) v = *(const float4*)(A + (long long)grow * 128 + acol);
        As[0][acol + 0][arow] = v.x;
        As[0][acol + 1][arow] = v.y;
        As[0][acol + 2][arow] = v.z;
        As[0][acol + 3][arow] = v.w;
        float4 wv = *(const float4*)(W + brow * 128 + bcol);
        *(float4*)&Bs[0][brow][bcol] = wv;
    }
    __syncthreads();

#pragma unroll 1
    for (int kk = 0; kk < 16; ++kk) {
        const int cur = kk & 1;
        float4 pa = make_float4(0.f, 0.f, 0.f, 0.f);
        float4 pb = make_float4(0.f, 0.f, 0.f, 0.f);
        if (kk < 15) {
            int grow = rowBase + arow;
            if (grow < M)
                pa = *(const float4*)(A + (long long)grow * 128 + (kk + 1) * 8 + acol);
            pb = *(const float4*)(W + ((kk + 1) * 8 + brow) * 128 + bcol);
        }
#pragma unroll
        for (int k = 0; k < 8; ++k) {
            const float4 a0 = *(const float4*)&As[cur][k][tr * 8];
            const float4 a1 = *(const float4*)&As[cur][k][tr * 8 + 4];
            const float4 b0 = *(const float4*)&Bs[cur][k][tc * 4];
            const float4 b1 = *(const float4*)&Bs[cur][k][tc * 4 + 64];
            const float ra[8] = {a0.x, a0.y, a0.z, a0.w, a1.x, a1.y, a1.z, a1.w};
            const float rb[8] = {b0.x, b0.y, b0.z, b0.w, b1.x, b1.y, b1.z, b1.w};
#pragma unroll
            for (int i = 0; i < 8; ++i)
#pragma unroll
                for (int j = 0; j < 8; ++j)
                    acc[i][j] = fmaf(ra[i], rb[j], acc[i][j]);
        }
        if (kk < 15) {
            const int nxt = cur ^ 1;
            As[nxt][acol + 0][arow] = pa.x;
            As[nxt][acol + 1][arow] = pa.y;
            As[nxt][acol + 2][arow] = pa.z;
            As[nxt][acol + 3][arow] = pa.w;
            *(float4*)&Bs[nxt][brow][bcol] = pb;
            __syncthreads();
        }
    }

    // epilogue: + bias, relu, store
    const float4 bb0 = *(const float4*)(bias + tc * 4);
    const float4 bb1 = *(const float4*)(bias + tc * 4 + 64);
#pragma unroll
    for (int i = 0; i < 8; ++i) {
        int grow = rowBase + tr * 8 + i;
        if (grow < M) {
            float4 c0, c1;
            c0.x = fmaxf(acc[i][0] + bb0.x, 0.f);
            c0.y = fmaxf(acc[i][1] + bb0.y, 0.f);
            c0.z = fmaxf(acc[i][2] + bb0.z, 0.f);
            c0.w = fmaxf(acc[i][3] + bb0.w, 0.f);
            c1.x = fmaxf(acc[i][4] + bb1.x, 0.f);
            c1.y = fmaxf(acc[i][5] + bb1.y, 0.f);
            c1.z = fmaxf(acc[i][6] + bb1.z, 0.f);
            c1.w = fmaxf(acc[i][7] + bb1.w, 0.f);
            *(float4*)(C + (long long)grow * 128 + tc * 4) = c0;
            *(float4*)(C + (long long)grow * 128 + tc * 4 + 64) = c1;
        }
    }
}

// ---------------------------------------------------------------------------
// out = log_softmax(H @ Wl + bl)   H:[M,128] Wl:[128,40]
// one warp per row; lane owns cols lane and lane+32 (if <40)
// ---------------------------------------------------------------------------
__global__ __launch_bounds__(256) void k_cls(int h_sel, const float* __restrict__ Wl,
                                             const float* __restrict__ bl,
                                             float* __restrict__ out, int M) {
    const float* H = bufsel(h_sel);
    __shared__ float sW[128 * 40];
    __shared__ float sb[40];
    __shared__ float srow[8][128];

    const int tid = threadIdx.x;
    for (int i = tid; i < 128 * 40; i += 256) sW[i] = Wl[i];
    if (tid < 40) sb[tid] = bl[tid];
    __syncthreads();

    const int warp = tid >> 5, lane = tid & 31;
    const long long r = (long long)blockIdx.x * 8 + warp;
    if (r >= M) return;

    ((float4*)srow[warp])[lane] = ((const float4*)(H + r * 128))[lane];
    __syncwarp();

    const int c0 = lane;
    const int c1 = lane + 32;
    float acc0 = sb[c0];
    float acc1 = (c1 < 40) ? sb[c1] : -1e30f;
#pragma unroll 4
    for (int f = 0; f < 128; ++f) {
        float hv = srow[warp][f];
        acc0 = fmaf(hv, sW[f * 40 + c0], acc0);
        if (c1 < 40) acc1 = fmaf(hv, sW[f * 40 + c1], acc1);
    }
    float mx = fmaxf(acc0, acc1);
#pragma unroll
    for (int o = 16; o; o >>= 1) mx = fmaxf(mx, __shfl_xor_sync(0xFFFFFFFFu, mx, o));
    float s = expf(acc0 - mx) + ((c1 < 40) ? expf(acc1 - mx) : 0.0f);
#pragma unroll
    for (int o = 16; o; o >>= 1) s += __shfl_xor_sync(0xFFFFFFFFu, s, o);
    float lse = mx + logf(s);
    out[r * 40 + c0] = acc0 - lse;
    if (c1 < 40) out[r * 40 + c1] = acc1 - lse;
}

// ---------------------------------------------------------------------------
extern "C" void kernel_launch(void* const* d_in, const int* in_sizes, int n_in,
                              void* d_out, int out_size) {
    const float* x   = (const float*)d_in[0];
    const void*  ei  = d_in[1];
    const float* ea  = (const float*)d_in[2];
    const float* eps1 = (const float*)d_in[3];
    const float* We1 = (const float*)d_in[4];
    const float* be1 = (const float*)d_in[5];
    const float* W11 = (const float*)d_in[6];
    const float* b11 = (const float*)d_in[7];
    const float* W12 = (const float*)d_in[8];
    const float* b12 = (const float*)d_in[9];
    const float* eps2 = (const float*)d_in[10];
    const float* We2 = (const float*)d_in[11];
    const float* be2 = (const float*)d_in[12];
    const float* W21 = (const float*)d_in[13];
    const float* b21 = (const float*)d_in[14];
    const float* W22 = (const float*)d_in[15];
    const float* b22 = (const float*)d_in[16];
    const float* Wl  = (const float*)d_in[17];
    const float* bl  = (const float*)d_in[18];
    float* out = (float*)d_out;

    const int N = in_sizes[0] / FDIM;
    const int E = in_sizes[2];

    const int n4 = N * (FDIM / 4);
    const int gs = (n4 + 255) / 256;
    const long long et = (long long)E * 32;
    const int ge = (int)((et + 255) / 256);
    const int gg = (N + 127) / 128;
    const int gc = (N + 7) / 8;

    k_detect<<<1, 32>>>((const long long*)ei, N);

    // conv1 (x external -> A), outer relu fused into 2nd GEMM
    k_scale<<<gs, 256>>>((const float4*)x, -1, 0, eps1, n4);
    k_edge<<<ge, 256>>>(ei, ea, (const float4*)x, -1, 0,
                        (const float4*)We1, (const float4*)be1, E);
    k_gemm_relu<<<gg, 256>>>(0, W11, b11, 1, N);   // B = relu(A@W11+b11)
    k_gemm_relu<<<gg, 256>>>(1, W12, b12, 0, N);   // A = relu(B@W12+b12)

    // conv2 (A -> B)
    k_scale<<<gs, 256>>>(nullptr, 0, 1, eps2, n4);
    k_edge<<<ge, 256>>>(ei, ea, nullptr, 0, 1,
                        (const float4*)We2, (const float4*)be2, E);
    k_gemm_relu<<<gg, 256>>>(1, W21, b21, 0, N);   // A = relu(B@W21+b21)
    k_gemm_relu<<<gg, 256>>>(0, W22, b22, 1, N);   // B = relu(A@W22+b22)

    // classifier + log_softmax
    k_cls<<<gc, 256>>>(1, Wl, bl, out, N);
}

// round 3
// speedup vs baseline: 1.3356x; 1.3356x over previous
#include <cuda_runtime.h>

// GINENet: 2x GINEConv(F=128) + classifier(40) + log_softmax
// N=100000, E=1600000, F=128.
//
// R3 == R2 resubmit (R2 bench died to container infra failure, same as the
// Round-0 stub run; code audited, unchanged):
// atomics-free aggregation. Per launch, build CSR over dst (histogram ->
// scan -> scatter into dst-sorted src/ea arrays, shared by both convs), then
// one-warp-per-node gather aggregation with (1+eps)*x fused in.

#define NODES_MAX 100000
#define EDGE_MAX  1600000
#define FDIM 128

__device__ float g_A[(size_t)NODES_MAX * FDIM];
__device__ float g_B[(size_t)NODES_MAX * FDIM];
__device__ int   g_rowptr[NODES_MAX + 1];
__device__ int   g_cur[NODES_MAX];
__device__ int   g_bsum[128];
__device__ int   g_srcS[EDGE_MAX];
__device__ float g_eaS[EDGE_MAX];
__device__ int   g_is64;

__device__ __forceinline__ float* bufsel(int s) { return (s == 0) ? g_A : g_B; }

// ---------------------------------------------------------------------------
// Detect int64 vs int32 edge_index (int32 read as int64 -> high word is a
// random index in [0,N), nonzero w.p. ~1-1e-5 per value).
// ---------------------------------------------------------------------------
__global__ void k_detect(const long long* __restrict__ ei, int n_nodes) {
    if (threadIdx.x == 0 && blockIdx.x == 0) {
        int ok = 1;
        for (int i = 0; i < 64; ++i) {
            long long v = ei[i];
            if (v < 0 || v >= (long long)n_nodes) { ok = 0; break; }
        }
        g_is64 = ok;
    }
}

__device__ __forceinline__ long long load_idx(const void* ei, long long off) {
    if (g_is64) return __ldg((const long long*)ei + off);
    return (long long)__ldg((const int*)ei + off);
}

// ---------------------------------------------------------------------------
// CSR build: zero -> histogram(dst) -> 3-phase exclusive scan -> scatter
// ---------------------------------------------------------------------------
__global__ void k_zero(int n) {
    int i = blockIdx.x * blockDim.x + threadIdx.x;
    if (i < n) g_cur[i] = 0;
}

__global__ void k_hist(const void* __restrict__ ei, int E) {
    int e = blockIdx.x * blockDim.x + threadIdx.x;
    if (e >= E) return;
    int dst = (int)load_idx(ei, (long long)E + e);
    atomicAdd(&g_cur[dst], 1);
}

// per-1024-block exclusive scan; block totals to g_bsum
__global__ void k_scan1(int n) {
    const int tid = threadIdx.x, lane = tid & 31, warp = tid >> 5;
    const int idx = blockIdx.x * 1024 + tid;
    int v = (idx < n) ? g_cur[idx] : 0;
    int inc = v;
#pragma unroll
    for (int o = 1; o < 32; o <<= 1) {
        int t = __shfl_up_sync(0xFFFFFFFFu, inc, o);
        if (lane >= o) inc += t;
    }
    __shared__ int ws[32];
    if (lane == 31) ws[warp] = inc;
    __syncthreads();
    if (warp == 0) {
        int wv = ws[lane];
        int winc = wv;
#pragma unroll
        for (int o = 1; o < 32; o <<= 1) {
            int t = __shfl_up_sync(0xFFFFFFFFu, winc, o);
            if (lane >= o) winc += t;
        }
        ws[lane] = winc - wv;   // exclusive warp offsets
    }
    __syncthreads();
    int excl = inc - v + ws[warp];
    if (idx <= n) g_rowptr[idx] = excl;   // block-local exclusive
    if (tid == 1023) g_bsum[blockIdx.x] = excl + v;  // block total
}

__global__ void k_scan2(int nb) {
    __shared__ int s[128];
    int t = threadIdx.x;
    s[t] = (t < nb) ? g_bsum[t] : 0;
    __syncthreads();
    if (t == 0) {
        int run = 0;
        for (int i = 0; i < nb; ++i) { int v = s[i]; s[i] = run; run += v; }
    }
    __syncthreads();
    g_bsum[t] = s[t];
}

__global__ void k_scan3(int n, int E) {
    int idx = blockIdx.x * blockDim.x + threadIdx.x;
    if (idx < n) {
        int r = g_rowptr[idx] + g_bsum[idx >> 10];
        g_rowptr[idx] = r;
        g_cur[idx] = r;
    }
    if (idx == 0) g_rowptr[n] = E;
}

__global__ void k_scatter(const void* __restrict__ ei, const float* __restrict__ ea,
                          int E) {
    int e = blockIdx.x * blockDim.x + threadIdx.x;
    if (e >= E) return;
    int src = (int)load_idx(ei, e);
    int dst = (int)load_idx(ei, (long long)E + e);
    int pos = atomicAdd(&g_cur[dst], 1);
    g_srcS[pos] = src;
    g_eaS[pos] = __ldg(ea + e);
}

// ---------------------------------------------------------------------------
// Aggregation: one warp per node, lane owns float4 column.
//   h[v] = (1+eps)*x[v] + sum_{e in CSR[v]} relu(x[src_e] + a_e*We + be)
// ---------------------------------------------------------------------------
__global__ __launch_bounds__(256) void k_aggr(
    const float4* __restrict__ x_ext, int x_sel, int out_sel,
    const float* __restrict__ eps,
    const float4* __restrict__ We4, const float4* __restrict__ be4, int N) {
    const int tid = threadIdx.x;
    const int warp = tid >> 5, lane = tid & 31;
    const int v = blockIdx.x * 8 + warp;
    if (v >= N) return;

    const float4* x4 = x_ext ? x_ext : (const float4*)bufsel(x_sel);
    float4* h4 = (float4*)bufsel(out_sel);

    const float s = 1.0f + __ldg(eps);
    const float4 w = __ldg(We4 + lane);
    const float4 b = __ldg(be4 + lane);

    float4 acc = __ldg(x4 + (long long)v * 32 + lane);
    acc.x *= s; acc.y *= s; acc.z *= s; acc.w *= s;

    int e = g_rowptr[v];
    const int end = g_rowptr[v + 1];
    int ps = 0; float pa = 0.0f;
    if (e < end) { ps = __ldg(g_srcS + e); pa = __ldg(g_eaS + e); }
    while (e < end) {
        const int src = ps;
        const float a = pa;
        ++e;
        if (e < end) { ps = __ldg(g_srcS + e); pa = __ldg(g_eaS + e); }
        const float4 xv = __ldg(x4 + (long long)src * 32 + lane);
        acc.x += fmaxf(fmaf(a, w.x, b.x) + xv.x, 0.0f);
        acc.y += fmaxf(fmaf(a, w.y, b.y) + xv.y, 0.0f);
        acc.z += fmaxf(fmaf(a, w.z, b.z) + xv.z, 0.0f);
        acc.w += fmaxf(fmaf(a, w.w, b.w) + xv.w, 0.0f);
    }
    h4[(long long)v * 32 + lane] = acc;
}

// ---------------------------------------------------------------------------
// C = relu(A @ W + bias)   A:[M,128] W:[128,128]
// 128x128 tile, 256 threads, 8x8 micro-tile, double-buffered over K (BK=8).
// ---------------------------------------------------------------------------
__global__ __launch_bounds__(256, 2) void k_gemm_relu(
    int a_sel, const float* __restrict__ W, const float* __restrict__ bias,
    int c_sel, int M) {
    const float* A = bufsel(a_sel);
    float* C = bufsel(c_sel);

    __shared__ float As[2][8][132];
    __shared__ float Bs[2][8][132];

    const int tid = threadIdx.x;
    const int tr = tid >> 4;
    const int tc = tid & 15;
    const int arow = tid >> 1;
    const int acol = (tid & 1) << 2;
    const int brow = tid >> 5;
    const int bcol = (tid & 31) << 2;
    const int rowBase = blockIdx.x * 128;

    float acc[8][8];
#pragma unroll
    for (int i = 0; i < 8; ++i)
#pragma unroll
        for (int j = 0; j < 8; ++j) acc[i][j] = 0.0f;

    {
        int grow = rowBase + arow;
        float4 v = make_float4(0.f, 0.f, 0.f, 0.f);
        if (grow < M) v = *(const float4*)(A + (long long)grow * 128 + acol);
        As[0][acol + 0][arow] = v.x;
        As[0][acol + 1][arow] = v.y;
        As[0][acol + 2][arow] = v.z;
        As[0][acol + 3][arow] = v.w;
        float4 wv = *(const float4*)(W + brow * 128 + bcol);
        *(float4*)&Bs[0][brow][bcol] = wv;
    }
    __syncthreads();

#pragma unroll 1
    for (int kk = 0; kk < 16; ++kk) {
        const int cur = kk & 1;
        float4 pa = make_float4(0.f, 0.f, 0.f, 0.f);
        float4 pb = make_float4(0.f, 0.f, 0.f, 0.f);
        if (kk < 15) {
            int grow = rowBase + arow;
            if (grow < M)
                pa = *(const float4*)(A + (long long)grow * 128 + (kk + 1) * 8 + acol);
            pb = *(const float4*)(W + ((kk + 1) * 8 + brow) * 128 + bcol);
        }
#pragma unroll
        for (int k = 0; k < 8; ++k) {
            const float4 a0 = *(const float4*)&As[cur][k][tr * 8];
            const float4 a1 = *(const float4*)&As[cur][k][tr * 8 + 4];
            const float4 b0 = *(const float4*)&Bs[cur][k][tc * 4];
            const float4 b1 = *(const float4*)&Bs[cur][k][tc * 4 + 64];
            const float ra[8] = {a0.x, a0.y, a0.z, a0.w, a1.x, a1.y, a1.z, a1.w};
            const float rb[8] = {b0.x, b0.y, b0.z, b0.w, b1.x, b1.y, b1.z, b1.w};
#pragma unroll
            for (int i = 0; i < 8; ++i)
#pragma unroll
                for (int j = 0; j < 8; ++j)
                    acc[i][j] = fmaf(ra[i], rb[j], acc[i][j]);
        }
        if (kk < 15) {
            const int nxt = cur ^ 1;
            As[nxt][acol + 0][arow] = pa.x;
            As[nxt][acol + 1][arow] = pa.y;
            As[nxt][acol + 2][arow] = pa.z;
            As[nxt][acol + 3][arow] = pa.w;
            *(float4*)&Bs[nxt][brow][bcol] = pb;
            __syncthreads();
        }
    }

    const float4 bb0 = *(const float4*)(bias + tc * 4);
    const float4 bb1 = *(const float4*)(bias + tc * 4 + 64);
#pragma unroll
    for (int i = 0; i < 8; ++i) {
        int grow = rowBase + tr * 8 + i;
        if (grow < M) {
            float4 c0, c1;
            c0.x = fmaxf(acc[i][0] + bb0.x, 0.f);
            c0.y = fmaxf(acc[i][1] + bb0.y, 0.f);
            c0.z = fmaxf(acc[i][2] + bb0.z, 0.f);
            c0.w = fmaxf(acc[i][3] + bb0.w, 0.f);
            c1.x = fmaxf(acc[i][4] + bb1.x, 0.f);
            c1.y = fmaxf(acc[i][5] + bb1.y, 0.f);
            c1.z = fmaxf(acc[i][6] + bb1.z, 0.f);
            c1.w = fmaxf(acc[i][7] + bb1.w, 0.f);
            *(float4*)(C + (long long)grow * 128 + tc * 4) = c0;
            *(float4*)(C + (long long)grow * 128 + tc * 4 + 64) = c1;
        }
    }
}

// ---------------------------------------------------------------------------
// out = log_softmax(H @ Wl + bl)
// ---------------------------------------------------------------------------
__global__ __launch_bounds__(256) void k_cls(int h_sel, const float* __restrict__ Wl,
                                             const float* __restrict__ bl,
                                             float* __restrict__ out, int M) {
    const float* H = bufsel(h_sel);
    __shared__ float sW[128 * 40];
    __shared__ float sb[40];
    __shared__ float srow[8][128];

    const int tid = threadIdx.x;
    for (int i = tid; i < 128 * 40; i += 256) sW[i] = Wl[i];
    if (tid < 40) sb[tid] = bl[tid];
    __syncthreads();

    const int warp = tid >> 5, lane = tid & 31;
    const long long r = (long long)blockIdx.x * 8 + warp;
    if (r >= M) return;

    ((float4*)srow[warp])[lane] = ((const float4*)(H + r * 128))[lane];
    __syncwarp();

    const int c0 = lane;
    const int c1 = lane + 32;
    float acc0 = sb[c0];
    float acc1 = (c1 < 40) ? sb[c1] : -1e30f;
#pragma unroll 4
    for (int f = 0; f < 128; ++f) {
        float hv = srow[warp][f];
        acc0 = fmaf(hv, sW[f * 40 + c0], acc0);
        if (c1 < 40) acc1 = fmaf(hv, sW[f * 40 + c1], acc1);
    }
    float mx = fmaxf(acc0, acc1);
#pragma unroll
    for (int o = 16; o; o >>= 1) mx = fmaxf(mx, __shfl_xor_sync(0xFFFFFFFFu, mx, o));
    float s = expf(acc0 - mx) + ((c1 < 40) ? expf(acc1 - mx) : 0.0f);
#pragma unroll
    for (int o = 16; o; o >>= 1) s += __shfl_xor_sync(0xFFFFFFFFu, s, o);
    float lse = mx + logf(s);
    out[r * 40 + c0] = acc0 - lse;
    if (c1 < 40) out[r * 40 + c1] = acc1 - lse;
}

// ---------------------------------------------------------------------------
extern "C" void kernel_launch(void* const* d_in, const int* in_sizes, int n_in,
                              void* d_out, int out_size) {
    const float* x   = (const float*)d_in[0];
    const void*  ei  = d_in[1];
    const float* ea  = (const float*)d_in[2];
    const float* eps1 = (const float*)d_in[3];
    const float* We1 = (const float*)d_in[4];
    const float* be1 = (const float*)d_in[5];
    const float* W11 = (const float*)d_in[6];
    const float* b11 = (const float*)d_in[7];
    const float* W12 = (const float*)d_in[8];
    const float* b12 = (const float*)d_in[9];
    const float* eps2 = (const float*)d_in[10];
    const float* We2 = (const float*)d_in[11];
    const float* be2 = (const float*)d_in[12];
    const float* W21 = (const float*)d_in[13];
    const float* b21 = (const float*)d_in[14];
    const float* W22 = (const float*)d_in[15];
    const float* b22 = (const float*)d_in[16];
    const float* Wl  = (const float*)d_in[17];
    const float* bl  = (const float*)d_in[18];
    float* out = (float*)d_out;

    const int N = in_sizes[0] / FDIM;
    const int E = in_sizes[2];

    const int gn = (N + 255) / 256;
    const int ge = (E + 255) / 256;
    const int nb = (N + 1023) / 1024;
    const int ga = (N + 7) / 8;
    const int gg = (N + 127) / 128;
    const int gc = (N + 7) / 8;

    // ---- CSR build (shared by both convs) ----
    k_detect<<<1, 32>>>((const long long*)ei, N);
    k_zero<<<gn, 256>>>(N);
    k_hist<<<ge, 256>>>(ei, E);
    k_scan1<<<nb, 1024>>>(N);
    k_scan2<<<1, 128>>>(nb);
    k_scan3<<<gn, 256>>>(N, E);
    k_scatter<<<ge, 256>>>(ei, ea, E);

    // ---- conv1: x (external) -> A ----
    k_aggr<<<ga, 256>>>((const float4*)x, -1, 0, eps1,
                        (const float4*)We1, (const float4*)be1, N);
    k_gemm_relu<<<gg, 256>>>(0, W11, b11, 1, N);
    k_gemm_relu<<<gg, 256>>>(1, W12, b12, 0, N);

    // ---- conv2: A -> B ----
    k_aggr<<<ga, 256>>>(nullptr, 0, 1, eps2,
                        (const float4*)We2, (const float4*)be2, N);
    k_gemm_relu<<<gg, 256>>>(1, W21, b21, 0, N);
    k_gemm_relu<<<gg, 256>>>(0, W22, b22, 1, N);

    // ---- classifier ----
    k_cls<<<gc, 256>>>(1, Wl, bl, out, N);
}

// round 5
// speedup vs baseline: 1.7806x; 1.3332x over previous
#include <cuda_runtime.h>
#include <cstdint>

// GINENet: 2x GINEConv(F=128) + classifier(40) + log_softmax
// N=100000, E=1600000, F=128.
//
// R5: fix R4's tf32 A-fragment layout bug (a1/a2 quadrants swapped).
// a0=A[g][c] a1=A[g+8][c] a2=A[g][c+4] a3=A[g+8][c+4], g=lane>>2, c=lane&3.
// Everything else unchanged from R4.

#define NODES_MAX 100000
#define EDGE_MAX  1600000
#define FDIM 128

__device__ float g_A[(size_t)NODES_MAX * FDIM];
__device__ float g_B[(size_t)NODES_MAX * FDIM];
__device__ int   g_rowptr[NODES_MAX + 1];
__device__ int   g_cur[NODES_MAX];
__device__ int   g_bsum[128];
__device__ int   g_srcS[EDGE_MAX];
__device__ float g_eaS[EDGE_MAX];
__device__ int   g_is64;

__device__ __forceinline__ float* bufsel(int s) { return (s == 0) ? g_A : g_B; }

__device__ __forceinline__ uint32_t f2tf32(float f) {
    uint32_t r;
    asm("cvt.rna.tf32.f32 %0, %1;" : "=r"(r) : "f"(f));
    return r;
}

__device__ __forceinline__ void mma_tf32(float* c, uint32_t a0, uint32_t a1,
                                         uint32_t a2, uint32_t a3,
                                         uint32_t b0, uint32_t b1) {
    asm volatile(
        "mma.sync.aligned.m16n8k8.row.col.f32.tf32.tf32.f32 "
        "{%0,%1,%2,%3}, {%4,%5,%6,%7}, {%8,%9}, {%0,%1,%2,%3};"
        : "+f"(c[0]), "+f"(c[1]), "+f"(c[2]), "+f"(c[3])
        : "r"(a0), "r"(a1), "r"(a2), "r"(a3), "r"(b0), "r"(b1));
}

// ---------------------------------------------------------------------------
// Detect int64 vs int32 edge_index.
// ---------------------------------------------------------------------------
__global__ void k_detect(const long long* __restrict__ ei, int n_nodes) {
    if (threadIdx.x == 0 && blockIdx.x == 0) {
        int ok = 1;
        for (int i = 0; i < 64; ++i) {
            long long v = ei[i];
            if (v < 0 || v >= (long long)n_nodes) { ok = 0; break; }
        }
        g_is64 = ok;
    }
}

__device__ __forceinline__ long long load_idx(const void* ei, long long off) {
    if (g_is64) return __ldg((const long long*)ei + off);
    return (long long)__ldg((const int*)ei + off);
}

// ---------------------------------------------------------------------------
// CSR build: zero -> histogram(dst) -> 3-phase exclusive scan -> scatter
// ---------------------------------------------------------------------------
__global__ void k_zero(int n) {
    int i = blockIdx.x * blockDim.x + threadIdx.x;
    if (i < n) g_cur[i] = 0;
}

__global__ void k_hist(const void* __restrict__ ei, int E) {
    int e = blockIdx.x * blockDim.x + threadIdx.x;
    if (e >= E) return;
    int dst = (int)load_idx(ei, (long long)E + e);
    atomicAdd(&g_cur[dst], 1);
}

__global__ void k_scan1(int n) {
    const int tid = threadIdx.x, lane = tid & 31, warp = tid >> 5;
    const int idx = blockIdx.x * 1024 + tid;
    int v = (idx < n) ? g_cur[idx] : 0;
    int inc = v;
#pragma unroll
    for (int o = 1; o < 32; o <<= 1) {
        int t = __shfl_up_sync(0xFFFFFFFFu, inc, o);
        if (lane >= o) inc += t;
    }
    __shared__ int ws[32];
    if (lane == 31) ws[warp] = inc;
    __syncthreads();
    if (warp == 0) {
        int wv = ws[lane];
        int winc = wv;
#pragma unroll
        for (int o = 1; o < 32; o <<= 1) {
            int t = __shfl_up_sync(0xFFFFFFFFu, winc, o);
            if (lane >= o) winc += t;
        }
        ws[lane] = winc - wv;
    }
    __syncthreads();
    int excl = inc - v + ws[warp];
    if (idx <= n) g_rowptr[idx] = excl;
    if (tid == 1023) g_bsum[blockIdx.x] = excl + v;
}

__global__ void k_scan2(int nb) {
    __shared__ int s[128];
    int t = threadIdx.x;
    s[t] = (t < nb) ? g_bsum[t] : 0;
    __syncthreads();
    if (t == 0) {
        int run = 0;
        for (int i = 0; i < nb; ++i) { int v = s[i]; s[i] = run; run += v; }
    }
    __syncthreads();
    g_bsum[t] = s[t];
}

__global__ void k_scan3(int n, int E) {
    int idx = blockIdx.x * blockDim.x + threadIdx.x;
    if (idx < n) {
        int r = g_rowptr[idx] + g_bsum[idx >> 10];
        g_rowptr[idx] = r;
        g_cur[idx] = r;
    }
    if (idx == 0) g_rowptr[n] = E;
}

__global__ void k_scatter(const void* __restrict__ ei, const float* __restrict__ ea,
                          int E) {
    int e = blockIdx.x * blockDim.x + threadIdx.x;
    if (e >= E) return;
    int src = (int)load_idx(ei, e);
    int dst = (int)load_idx(ei, (long long)E + e);
    int pos = atomicAdd(&g_cur[dst], 1);
    g_srcS[pos] = src;
    g_eaS[pos] = __ldg(ea + e);
}

// ---------------------------------------------------------------------------
// Aggregation: one warp per node, lane owns float4 column.
//   h[v] = (1+eps)*x[v] + sum_{e in CSR[v]} relu(x[src_e] + a_e*We + be)
// ---------------------------------------------------------------------------
__global__ __launch_bounds__(256) void k_aggr(
    const float4* __restrict__ x_ext, int x_sel, int out_sel,
    const float* __restrict__ eps,
    const float4* __restrict__ We4, const float4* __restrict__ be4, int N) {
    const int tid = threadIdx.x;
    const int warp = tid >> 5, lane = tid & 31;
    const int v = blockIdx.x * 8 + warp;
    if (v >= N) return;

    const float4* x4 = x_ext ? x_ext : (const float4*)bufsel(x_sel);
    float4* h4 = (float4*)bufsel(out_sel);

    const float s = 1.0f + __ldg(eps);
    const float4 w = __ldg(We4 + lane);
    const float4 b = __ldg(be4 + lane);

    float4 acc = __ldg(x4 + (long long)v * 32 + lane);
    acc.x *= s; acc.y *= s; acc.z *= s; acc.w *= s;

    int e = g_rowptr[v];
    const int end = g_rowptr[v + 1];
    int ps = 0; float pa = 0.0f;
    if (e < end) { ps = __ldg(g_srcS + e); pa = __ldg(g_eaS + e); }
    while (e < end) {
        const int src = ps;
        const float a = pa;
        ++e;
        if (e < end) { ps = __ldg(g_srcS + e); pa = __ldg(g_eaS + e); }
        const float4 xv = __ldg(x4 + (long long)src * 32 + lane);
        acc.x += fmaxf(fmaf(a, w.x, b.x) + xv.x, 0.0f);
        acc.y += fmaxf(fmaf(a, w.y, b.y) + xv.y, 0.0f);
        acc.z += fmaxf(fmaf(a, w.z, b.z) + xv.z, 0.0f);
        acc.w += fmaxf(fmaf(a, w.w, b.w) + xv.w, 0.0f);
    }
    h4[(long long)v * 32 + lane] = acc;
}

// ---------------------------------------------------------------------------
// C = relu(A @ W + bias) via tf32 mma.sync.m16n8k8, fp32 accumulate.
// Block tile 128x128, 8 warps (warp tile 64x32 = 4x4 mma frags),
// BK=16, double-buffered A (pad 20) and W (pad 136) in smem.
// ---------------------------------------------------------------------------
#define APAD 20
#define WPAD 136

__global__ __launch_bounds__(256, 2) void k_gemm_tf32(
    int a_sel, const float* __restrict__ W, const float* __restrict__ bias,
    int c_sel, int M) {
    const float* A = bufsel(a_sel);
    float* C = bufsel(c_sel);

    __shared__ float As[2][128 * APAD];   // [m][k] 128x16, pad 20
    __shared__ float Ws[2][16 * WPAD];    // [k][n] 16x128, pad 136

    const int tid = threadIdx.x;
    const int lane = tid & 31;
    const int wid = tid >> 5;
    const int warp_m = wid & 1;           // 0..1  -> 64-row half
    const int warp_n = wid >> 1;          // 0..3  -> 32-col quarter
    const int rowBase = blockIdx.x * 128;

    float acc[4][4][4];
#pragma unroll
    for (int i = 0; i < 4; ++i)
#pragma unroll
        for (int j = 0; j < 4; ++j)
#pragma unroll
            for (int q = 0; q < 4; ++q) acc[i][j][q] = 0.0f;

    // loader mappings (2 float4 per thread per tile per chunk)
    const int a_row0 = tid >> 2;              // it0: rows 0..63
    const int a_c4 = (tid & 3) << 2;          // cols 0..12 step 4 (of 16)
    const int w_k0 = tid >> 5;                // it0: k 0..7
    const int w_c4 = (tid & 31) << 2;         // cols 0..124

    // ---- stage chunk 0 ----
    {
#pragma unroll
        for (int it = 0; it < 2; ++it) {
            int row = a_row0 + it * 64;
            int grow = rowBase + row;
            float4 v = make_float4(0.f, 0.f, 0.f, 0.f);
            if (grow < M) v = __ldg((const float4*)(A + (long long)grow * 128 + a_c4));
            float* d = &As[0][row * APAD + a_c4];
            d[0] = __uint_as_float(f2tf32(v.x));
            d[1] = __uint_as_float(f2tf32(v.y));
            d[2] = __uint_as_float(f2tf32(v.z));
            d[3] = __uint_as_float(f2tf32(v.w));
            int k = w_k0 + it * 8;
            float4 wv = __ldg((const float4*)(W + k * 128 + w_c4));
            float* e = &Ws[0][k * WPAD + w_c4];
            e[0] = __uint_as_float(f2tf32(wv.x));
            e[1] = __uint_as_float(f2tf32(wv.y));
            e[2] = __uint_as_float(f2tf32(wv.z));
            e[3] = __uint_as_float(f2tf32(wv.w));
        }
    }
    __syncthreads();

#pragma unroll 1
    for (int kc = 0; kc < 8; ++kc) {
        const int cur = kc & 1;
        float4 pa[2], pw[2];
        if (kc < 7) {
#pragma unroll
            for (int it = 0; it < 2; ++it) {
                int row = a_row0 + it * 64;
                int grow = rowBase + row;
                pa[it] = make_float4(0.f, 0.f, 0.f, 0.f);
                if (grow < M)
                    pa[it] = __ldg((const float4*)(A + (long long)grow * 128 +
                                                   (kc + 1) * 16 + a_c4));
                int k = w_k0 + it * 8;
                pw[it] = __ldg((const float4*)(W + ((kc + 1) * 16 + k) * 128 + w_c4));
            }
        }

        // ---- 2 k-steps of 8 within the chunk ----
#pragma unroll
        for (int ks = 0; ks < 2; ++ks) {
            const int k = ks * 8;
            uint32_t aF[4][4];
            uint32_t bF[4][2];
#pragma unroll
            for (int mt = 0; mt < 4; ++mt) {
                const int m = warp_m * 64 + mt * 16 + (lane >> 2);
                const float* p0 = &As[cur][m * APAD + k + (lane & 3)];
                const float* p1 = &As[cur][(m + 8) * APAD + k + (lane & 3)];
                aF[mt][0] = __float_as_uint(p0[0]);   // A[g   ][c  ]
                aF[mt][1] = __float_as_uint(p1[0]);   // A[g+8 ][c  ]
                aF[mt][2] = __float_as_uint(p0[4]);   // A[g   ][c+4]
                aF[mt][3] = __float_as_uint(p1[4]);   // A[g+8 ][c+4]
            }
#pragma unroll
            for (int nt = 0; nt < 4; ++nt) {
                const int n = warp_n * 32 + nt * 8 + (lane >> 2);
                bF[nt][0] = __float_as_uint(Ws[cur][(k + (lane & 3)) * WPAD + n]);
                bF[nt][1] = __float_as_uint(Ws[cur][(k + 4 + (lane & 3)) * WPAD + n]);
            }
#pragma unroll
            for (int mt = 0; mt < 4; ++mt)
#pragma unroll
                for (int nt = 0; nt < 4; ++nt)
                    mma_tf32(acc[mt][nt], aF[mt][0], aF[mt][1], aF[mt][2], aF[mt][3],
                             bF[nt][0], bF[nt][1]);
        }

        if (kc < 7) {
            const int nxt = cur ^ 1;
#pragma unroll
            for (int it = 0; it < 2; ++it) {
                int row = a_row0 + it * 64;
                float* d = &As[nxt][row * APAD + a_c4];
                d[0] = __uint_as_float(f2tf32(pa[it].x));
                d[1] = __uint_as_float(f2tf32(pa[it].y));
                d[2] = __uint_as_float(f2tf32(pa[it].z));
                d[3] = __uint_as_float(f2tf32(pa[it].w));
                int kk = w_k0 + it * 8;
                float* e = &Ws[nxt][kk * WPAD + w_c4];
                e[0] = __uint_as_float(f2tf32(pw[it].x));
                e[1] = __uint_as_float(f2tf32(pw[it].y));
                e[2] = __uint_as_float(f2tf32(pw[it].z));
                e[3] = __uint_as_float(f2tf32(pw[it].w));
            }
            __syncthreads();
        }
    }

    // ---- epilogue: +bias, relu, store (float2 per frag half) ----
#pragma unroll
    for (int nt = 0; nt < 4; ++nt) {
        const int col = warp_n * 32 + nt * 8 + ((lane & 3) << 1);
        const float bx = __ldg(bias + col);
        const float by = __ldg(bias + col + 1);
#pragma unroll
        for (int mt = 0; mt < 4; ++mt) {
            const int row0 = rowBase + warp_m * 64 + mt * 16 + (lane >> 2);
            if (row0 < M) {
                float2 v;
                v.x = fmaxf(acc[mt][nt][0] + bx, 0.0f);
                v.y = fmaxf(acc[mt][nt][1] + by, 0.0f);
                *(float2*)(C + (long long)row0 * 128 + col) = v;
            }
            const int row1 = row0 + 8;
            if (row1 < M) {
                float2 v;
                v.x = fmaxf(acc[mt][nt][2] + bx, 0.0f);
                v.y = fmaxf(acc[mt][nt][3] + by, 0.0f);
                *(float2*)(C + (long long)row1 * 128 + col) = v;
            }
        }
    }
}

// ---------------------------------------------------------------------------
// out = log_softmax(H @ Wl + bl)
// ---------------------------------------------------------------------------
__global__ __launch_bounds__(256) void k_cls(int h_sel, const float* __restrict__ Wl,
                                             const float* __restrict__ bl,
                                             float* __restrict__ out, int M) {
    const float* H = bufsel(h_sel);
    __shared__ float sW[128 * 40];
    __shared__ float sb[40];
    __shared__ float srow[8][128];

    const int tid = threadIdx.x;
    for (int i = tid; i < 128 * 40; i += 256) sW[i] = Wl[i];
    if (tid < 40) sb[tid] = bl[tid];
    __syncthreads();

    const int warp = tid >> 5, lane = tid & 31;
    const long long r = (long long)blockIdx.x * 8 + warp;
    if (r >= M) return;

    ((float4*)srow[warp])[lane] = ((const float4*)(H + r * 128))[lane];
    __syncwarp();

    const int c0 = lane;
    const int c1 = lane + 32;
    float acc0 = sb[c0];
    float acc1 = (c1 < 40) ? sb[c1] : -1e30f;
#pragma unroll 4
    for (int f = 0; f < 128; ++f) {
        float hv = srow[warp][f];
        acc0 = fmaf(hv, sW[f * 40 + c0], acc0);
        if (c1 < 40) acc1 = fmaf(hv, sW[f * 40 + c1], acc1);
    }
    float mx = fmaxf(acc0, acc1);
#pragma unroll
    for (int o = 16; o; o >>= 1) mx = fmaxf(mx, __shfl_xor_sync(0xFFFFFFFFu, mx, o));
    float s = expf(acc0 - mx) + ((c1 < 40) ? expf(acc1 - mx) : 0.0f);
#pragma unroll
    for (int o = 16; o; o >>= 1) s += __shfl_xor_sync(0xFFFFFFFFu, s, o);
    float lse = mx + logf(s);
    out[r * 40 + c0] = acc0 - lse;
    if (c1 < 40) out[r * 40 + c1] = acc1 - lse;
}

// ---------------------------------------------------------------------------
extern "C" void kernel_launch(void* const* d_in, const int* in_sizes, int n_in,
                              void* d_out, int out_size) {
    const float* x   = (const float*)d_in[0];
    const void*  ei  = d_in[1];
    const float* ea  = (const float*)d_in[2];
    const float* eps1 = (const float*)d_in[3];
    const float* We1 = (const float*)d_in[4];
    const float* be1 = (const float*)d_in[5];
    const float* W11 = (const float*)d_in[6];
    const float* b11 = (const float*)d_in[7];
    const float* W12 = (const float*)d_in[8];
    const float* b12 = (const float*)d_in[9];
    const float* eps2 = (const float*)d_in[10];
    const float* We2 = (const float*)d_in[11];
    const float* be2 = (const float*)d_in[12];
    const float* W21 = (const float*)d_in[13];
    const float* b21 = (const float*)d_in[14];
    const float* W22 = (const float*)d_in[15];
    const float* b22 = (const float*)d_in[16];
    const float* Wl  = (const float*)d_in[17];
    const float* bl  = (const float*)d_in[18];
    float* out = (float*)d_out;

    const int N = in_sizes[0] / FDIM;
    const int E = in_sizes[2];

    const int gn = (N + 255) / 256;
    const int ge = (E + 255) / 256;
    const int nb = (N + 1023) / 1024;
    const int ga = (N + 7) / 8;
    const int gg = (N + 127) / 128;
    const int gc = (N + 7) / 8;

    // ---- CSR build (shared by both convs) ----
    k_detect<<<1, 32>>>((const long long*)ei, N);
    k_zero<<<gn, 256>>>(N);
    k_hist<<<ge, 256>>>(ei, E);
    k_scan1<<<nb, 1024>>>(N);
    k_scan2<<<1, 128>>>(nb);
    k_scan3<<<gn, 256>>>(N, E);
    k_scatter<<<ge, 256>>>(ei, ea, E);

    // ---- conv1: x (external) -> A ----
    k_aggr<<<ga, 256>>>((const float4*)x, -1, 0, eps1,
                        (const float4*)We1, (const float4*)be1, N);
    k_gemm_tf32<<<gg, 256>>>(0, W11, b11, 1, N);
    k_gemm_tf32<<<gg, 256>>>(1, W12, b12, 0, N);

    // ---- conv2: A -> B ----
    k_aggr<<<ga, 256>>>(nullptr, 0, 1, eps2,
                        (const float4*)We2, (const float4*)be2, N);
    k_gemm_tf32<<<gg, 256>>>(1, W21, b21, 0, N);
    k_gemm_tf32<<<gg, 256>>>(0, W22, b22, 1, N);

    // ---- classifier ----
    k_cls<<<gc, 256>>>(1, Wl, bl, out, N);
}

// round 6
// speedup vs baseline: 1.9166x; 1.0764x over previous
#include <cuda_runtime.h>
#include <cstdint>

// GINENet: 2x GINEConv(F=128) + classifier(40) + log_softmax
// N=100000, E=1600000, F=128.
//
// R6: (a) fuse each conv's 2-GEMM MLP into one kernel (T tile lives in smem,
// W chunks double-buffered; intermediate never touches global), (b) 2-wide
// unrolled edge gather in k_aggr for MLP=2.

#define NODES_MAX 100000
#define EDGE_MAX  1600000
#define FDIM 128

#define APAD 20
#define WPAD 136
#define TPAD 132

__device__ float g_A[(size_t)NODES_MAX * FDIM];
__device__ float g_B[(size_t)NODES_MAX * FDIM];
__device__ int   g_rowptr[NODES_MAX + 1];
__device__ int   g_cur[NODES_MAX];
__device__ int   g_bsum[128];
__device__ int   g_srcS[EDGE_MAX];
__device__ float g_eaS[EDGE_MAX];
__device__ int   g_is64;

__device__ __forceinline__ float* bufsel(int s) { return (s == 0) ? g_A : g_B; }

__device__ __forceinline__ uint32_t f2tf32(float f) {
    uint32_t r;
    asm("cvt.rna.tf32.f32 %0, %1;" : "=r"(r) : "f"(f));
    return r;
}

__device__ __forceinline__ void mma_tf32(float* c, uint32_t a0, uint32_t a1,
                                         uint32_t a2, uint32_t a3,
                                         uint32_t b0, uint32_t b1) {
    asm volatile(
        "mma.sync.aligned.m16n8k8.row.col.f32.tf32.tf32.f32 "
        "{%0,%1,%2,%3}, {%4,%5,%6,%7}, {%8,%9}, {%0,%1,%2,%3};"
        : "+f"(c[0]), "+f"(c[1]), "+f"(c[2]), "+f"(c[3])
        : "r"(a0), "r"(a1), "r"(a2), "r"(a3), "r"(b0), "r"(b1));
}

// ---------------------------------------------------------------------------
// Detect int64 vs int32 edge_index.
// ---------------------------------------------------------------------------
__global__ void k_detect(const long long* __restrict__ ei, int n_nodes) {
    if (threadIdx.x == 0 && blockIdx.x == 0) {
        int ok = 1;
        for (int i = 0; i < 64; ++i) {
            long long v = ei[i];
            if (v < 0 || v >= (long long)n_nodes) { ok = 0; break; }
        }
        g_is64 = ok;
    }
}

__device__ __forceinline__ long long load_idx(const void* ei, long long off) {
    if (g_is64) return __ldg((const long long*)ei + off);
    return (long long)__ldg((const int*)ei + off);
}

// ---------------------------------------------------------------------------
// CSR build: zero -> histogram(dst) -> 3-phase exclusive scan -> scatter
// ---------------------------------------------------------------------------
__global__ void k_zero(int n) {
    int i = blockIdx.x * blockDim.x + threadIdx.x;
    if (i < n) g_cur[i] = 0;
}

__global__ void k_hist(const void* __restrict__ ei, int E) {
    int e = blockIdx.x * blockDim.x + threadIdx.x;
    if (e >= E) return;
    int dst = (int)load_idx(ei, (long long)E + e);
    atomicAdd(&g_cur[dst], 1);
}

__global__ void k_scan1(int n) {
    const int tid = threadIdx.x, lane = tid & 31, warp = tid >> 5;
    const int idx = blockIdx.x * 1024 + tid;
    int v = (idx < n) ? g_cur[idx] : 0;
    int inc = v;
#pragma unroll
    for (int o = 1; o < 32; o <<= 1) {
        int t = __shfl_up_sync(0xFFFFFFFFu, inc, o);
        if (lane >= o) inc += t;
    }
    __shared__ int ws[32];
    if (lane == 31) ws[warp] = inc;
    __syncthreads();
    if (warp == 0) {
        int wv = ws[lane];
        int winc = wv;
#pragma unroll
        for (int o = 1; o < 32; o <<= 1) {
            int t = __shfl_up_sync(0xFFFFFFFFu, winc, o);
            if (lane >= o) winc += t;
        }
        ws[lane] = winc - wv;
    }
    __syncthreads();
    int excl = inc - v + ws[warp];
    if (idx <= n) g_rowptr[idx] = excl;
    if (tid == 1023) g_bsum[blockIdx.x] = excl + v;
}

__global__ void k_scan2(int nb) {
    __shared__ int s[128];
    int t = threadIdx.x;
    s[t] = (t < nb) ? g_bsum[t] : 0;
    __syncthreads();
    if (t == 0) {
        int run = 0;
        for (int i = 0; i < nb; ++i) { int v = s[i]; s[i] = run; run += v; }
    }
    __syncthreads();
    g_bsum[t] = s[t];
}

__global__ void k_scan3(int n, int E) {
    int idx = blockIdx.x * blockDim.x + threadIdx.x;
    if (idx < n) {
        int r = g_rowptr[idx] + g_bsum[idx >> 10];
        g_rowptr[idx] = r;
        g_cur[idx] = r;
    }
    if (idx == 0) g_rowptr[n] = E;
}

__global__ void k_scatter(const void* __restrict__ ei, const float* __restrict__ ea,
                          int E) {
    int e = blockIdx.x * blockDim.x + threadIdx.x;
    if (e >= E) return;
    int src = (int)load_idx(ei, e);
    int dst = (int)load_idx(ei, (long long)E + e);
    int pos = atomicAdd(&g_cur[dst], 1);
    g_srcS[pos] = src;
    g_eaS[pos] = __ldg(ea + e);
}

// ---------------------------------------------------------------------------
// Aggregation: one warp per node, lane owns float4 column, 2-wide unroll.
//   h[v] = (1+eps)*x[v] + sum_{e in CSR[v]} relu(x[src_e] + a_e*We + be)
// ---------------------------------------------------------------------------
__global__ __launch_bounds__(256) void k_aggr(
    const float4* __restrict__ x_ext, int x_sel, int out_sel,
    const float* __restrict__ eps,
    const float4* __restrict__ We4, const float4* __restrict__ be4, int N) {
    const int tid = threadIdx.x;
    const int warp = tid >> 5, lane = tid & 31;
    const int v = blockIdx.x * 8 + warp;
    if (v >= N) return;

    const float4* x4 = x_ext ? x_ext : (const float4*)bufsel(x_sel);
    float4* h4 = (float4*)bufsel(out_sel);

    const float s = 1.0f + __ldg(eps);
    const float4 w = __ldg(We4 + lane);
    const float4 b = __ldg(be4 + lane);

    float4 acc = __ldg(x4 + (long long)v * 32 + lane);
    acc.x *= s; acc.y *= s; acc.z *= s; acc.w *= s;

    int e = g_rowptr[v];
    const int end = g_rowptr[v + 1];
#pragma unroll 1
    for (; e + 2 <= end; e += 2) {
        const int s0 = __ldg(g_srcS + e);
        const int s1 = __ldg(g_srcS + e + 1);
        const float a0 = __ldg(g_eaS + e);
        const float a1 = __ldg(g_eaS + e + 1);
        const float4 x0 = __ldg(x4 + (long long)s0 * 32 + lane);
        const float4 x1 = __ldg(x4 + (long long)s1 * 32 + lane);
        acc.x += fmaxf(fmaf(a0, w.x, b.x) + x0.x, 0.0f) +
                 fmaxf(fmaf(a1, w.x, b.x) + x1.x, 0.0f);
        acc.y += fmaxf(fmaf(a0, w.y, b.y) + x0.y, 0.0f) +
                 fmaxf(fmaf(a1, w.y, b.y) + x1.y, 0.0f);
        acc.z += fmaxf(fmaf(a0, w.z, b.z) + x0.z, 0.0f) +
                 fmaxf(fmaf(a1, w.z, b.z) + x1.z, 0.0f);
        acc.w += fmaxf(fmaf(a0, w.w, b.w) + x0.w, 0.0f) +
                 fmaxf(fmaf(a1, w.w, b.w) + x1.w, 0.0f);
    }
    if (e < end) {
        const int s0 = __ldg(g_srcS + e);
        const float a0 = __ldg(g_eaS + e);
        const float4 x0 = __ldg(x4 + (long long)s0 * 32 + lane);
        acc.x += fmaxf(fmaf(a0, w.x, b.x) + x0.x, 0.0f);
        acc.y += fmaxf(fmaf(a0, w.y, b.y) + x0.y, 0.0f);
        acc.z += fmaxf(fmaf(a0, w.z, b.z) + x0.z, 0.0f);
        acc.w += fmaxf(fmaf(a0, w.w, b.w) + x0.w, 0.0f);
    }
    h4[(long long)v * 32 + lane] = acc;
}

// ---------------------------------------------------------------------------
// Fused MLP: C = relu( relu(A@W1 + b1) @ W2 + b2 )
// Block tile 128 rows x full 128 cols; T tile (tf32-rounded) kept in smem.
// tf32 mma.sync.m16n8k8, fp32 accumulate. Dyn smem ~105.5KB, 2 CTAs/SM.
// ---------------------------------------------------------------------------
__global__ __launch_bounds__(256, 2) void k_mlp(
    int a_sel, const float* __restrict__ W1, const float* __restrict__ b1,
    const float* __restrict__ W2, const float* __restrict__ b2,
    int c_sel, int M) {
    const float* A = bufsel(a_sel);
    float* C = bufsel(c_sel);

    extern __shared__ float smem[];
    float* As = smem;                       // 2 x 128 x APAD
    float* Ws = As + 2 * 128 * APAD;        // 2 x 16 x WPAD (reused for W2)
    float* Ts = Ws + 2 * 16 * WPAD;         // 128 x TPAD

    const int tid = threadIdx.x;
    const int lane = tid & 31;
    const int wid = tid >> 5;
    const int warp_m = wid & 1;
    const int warp_n = wid >> 1;
    const int rowBase = blockIdx.x * 128;

    const int g = lane >> 2;                 // fragment row group
    const int c = lane & 3;                  // fragment col-in-quad

    float acc[4][4][4];
#pragma unroll
    for (int i = 0; i < 4; ++i)
#pragma unroll
        for (int j = 0; j < 4; ++j)
#pragma unroll
            for (int q = 0; q < 4; ++q) acc[i][j][q] = 0.0f;

    const int a_row0 = tid >> 2;
    const int a_c4 = (tid & 3) << 2;
    const int w_k0 = tid >> 5;
    const int w_c4 = (tid & 31) << 2;

    // ================= GEMM 1: T = relu(A @ W1 + b1) =================
    {
#pragma unroll
        for (int it = 0; it < 2; ++it) {
            int row = a_row0 + it * 64;
            int grow = rowBase + row;
            float4 v = make_float4(0.f, 0.f, 0.f, 0.f);
            if (grow < M) v = __ldg((const float4*)(A + (long long)grow * 128 + a_c4));
            float* d = &As[row * APAD + a_c4];
            d[0] = __uint_as_float(f2tf32(v.x));
            d[1] = __uint_as_float(f2tf32(v.y));
            d[2] = __uint_as_float(f2tf32(v.z));
            d[3] = __uint_as_float(f2tf32(v.w));
            int k = w_k0 + it * 8;
            float4 wv = __ldg((const float4*)(W1 + k * 128 + w_c4));
            float* e = &Ws[k * WPAD + w_c4];
            e[0] = __uint_as_float(f2tf32(wv.x));
            e[1] = __uint_as_float(f2tf32(wv.y));
            e[2] = __uint_as_float(f2tf32(wv.z));
            e[3] = __uint_as_float(f2tf32(wv.w));
        }
    }
    __syncthreads();

#pragma unroll 1
    for (int kc = 0; kc < 8; ++kc) {
        const int cur = kc & 1;
        float4 pa[2], pw[2];
        if (kc < 7) {
#pragma unroll
            for (int it = 0; it < 2; ++it) {
                int row = a_row0 + it * 64;
                int grow = rowBase + row;
                pa[it] = make_float4(0.f, 0.f, 0.f, 0.f);
                if (grow < M)
                    pa[it] = __ldg((const float4*)(A + (long long)grow * 128 +
                                                   (kc + 1) * 16 + a_c4));
                int k = w_k0 + it * 8;
                pw[it] = __ldg((const float4*)(W1 + ((kc + 1) * 16 + k) * 128 + w_c4));
            }
        }
#pragma unroll
        for (int ks = 0; ks < 2; ++ks) {
            const int k = ks * 8;
            uint32_t aF[4][4], bF[4][2];
#pragma unroll
            for (int mt = 0; mt < 4; ++mt) {
                const int m = warp_m * 64 + mt * 16 + g;
                const float* p0 = &As[(cur * 128 + m) * APAD + k + c];
                const float* p1 = &As[(cur * 128 + m + 8) * APAD + k + c];
                aF[mt][0] = __float_as_uint(p0[0]);
                aF[mt][1] = __float_as_uint(p1[0]);
                aF[mt][2] = __float_as_uint(p0[4]);
                aF[mt][3] = __float_as_uint(p1[4]);
            }
#pragma unroll
            for (int nt = 0; nt < 4; ++nt) {
                const int n = warp_n * 32 + nt * 8 + g;
                bF[nt][0] = __float_as_uint(Ws[(cur * 16 + k + c) * WPAD + n]);
                bF[nt][1] = __float_as_uint(Ws[(cur * 16 + k + 4 + c) * WPAD + n]);
            }
#pragma unroll
            for (int mt = 0; mt < 4; ++mt)
#pragma unroll
                for (int nt = 0; nt < 4; ++nt)
                    mma_tf32(acc[mt][nt], aF[mt][0], aF[mt][1], aF[mt][2], aF[mt][3],
                             bF[nt][0], bF[nt][1]);
        }
        if (kc < 7) {
            const int nxt = cur ^ 1;
#pragma unroll
            for (int it = 0; it < 2; ++it) {
                int row = a_row0 + it * 64;
                float* d = &As[(nxt * 128 + row) * APAD + a_c4];
                d[0] = __uint_as_float(f2tf32(pa[it].x));
                d[1] = __uint_as_float(f2tf32(pa[it].y));
                d[2] = __uint_as_float(f2tf32(pa[it].z));
                d[3] = __uint_as_float(f2tf32(pa[it].w));
                int kk = w_k0 + it * 8;
                float* e = &Ws[(nxt * 16 + kk) * WPAD + w_c4];
                e[0] = __uint_as_float(f2tf32(pw[it].x));
                e[1] = __uint_as_float(f2tf32(pw[it].y));
                e[2] = __uint_as_float(f2tf32(pw[it].z));
                e[3] = __uint_as_float(f2tf32(pw[it].w));
            }
            __syncthreads();
        }
    }

    // epilogue 1: T = relu(acc + b1), tf32-rounded, into Ts; reset acc
#pragma unroll
    for (int nt = 0; nt < 4; ++nt) {
        const int col = warp_n * 32 + nt * 8 + (c << 1);
        const float bx = __ldg(b1 + col);
        const float by = __ldg(b1 + col + 1);
#pragma unroll
        for (int mt = 0; mt < 4; ++mt) {
            const int r0 = warp_m * 64 + mt * 16 + g;
            Ts[r0 * TPAD + col]     = __uint_as_float(f2tf32(fmaxf(acc[mt][nt][0] + bx, 0.0f)));
            Ts[r0 * TPAD + col + 1] = __uint_as_float(f2tf32(fmaxf(acc[mt][nt][1] + by, 0.0f)));
            Ts[(r0 + 8) * TPAD + col]     = __uint_as_float(f2tf32(fmaxf(acc[mt][nt][2] + bx, 0.0f)));
            Ts[(r0 + 8) * TPAD + col + 1] = __uint_as_float(f2tf32(fmaxf(acc[mt][nt][3] + by, 0.0f)));
#pragma unroll
            for (int q = 0; q < 4; ++q) acc[mt][nt][q] = 0.0f;
        }
    }
    __syncthreads();

    // ================= GEMM 2: C = relu(T @ W2 + b2) =================
    {
#pragma unroll
        for (int it = 0; it < 2; ++it) {
            int k = w_k0 + it * 8;
            float4 wv = __ldg((const float4*)(W2 + k * 128 + w_c4));
            float* e = &Ws[k * WPAD + w_c4];
            e[0] = __uint_as_float(f2tf32(wv.x));
            e[1] = __uint_as_float(f2tf32(wv.y));
            e[2] = __uint_as_float(f2tf32(wv.z));
            e[3] = __uint_as_float(f2tf32(wv.w));
        }
    }
    __syncthreads();

#pragma unroll 1
    for (int kc = 0; kc < 8; ++kc) {
        const int cur = kc & 1;
        float4 pw[2];
        if (kc < 7) {
#pragma unroll
            for (int it = 0; it < 2; ++it) {
                int k = w_k0 + it * 8;
                pw[it] = __ldg((const float4*)(W2 + ((kc + 1) * 16 + k) * 128 + w_c4));
            }
        }
#pragma unroll
        for (int ks = 0; ks < 2; ++ks) {
            const int k = kc * 16 + ks * 8;   // T column (K of GEMM2)
            uint32_t aF[4][4], bF[4][2];
#pragma unroll
            for (int mt = 0; mt < 4; ++mt) {
                const int m = warp_m * 64 + mt * 16 + g;
                const float* p0 = &Ts[m * TPAD + k + c];
                const float* p1 = &Ts[(m + 8) * TPAD + k + c];
                aF[mt][0] = __float_as_uint(p0[0]);
                aF[mt][1] = __float_as_uint(p1[0]);
                aF[mt][2] = __float_as_uint(p0[4]);
                aF[mt][3] = __float_as_uint(p1[4]);
            }
#pragma unroll
            for (int nt = 0; nt < 4; ++nt) {
                const int n = warp_n * 32 + nt * 8 + g;
                bF[nt][0] = __float_as_uint(Ws[(cur * 16 + (ks * 8) + c) * WPAD + n]);
                bF[nt][1] = __float_as_uint(Ws[(cur * 16 + (ks * 8) + 4 + c) * WPAD + n]);
            }
#pragma unroll
            for (int mt = 0; mt < 4; ++mt)
#pragma unroll
                for (int nt = 0; nt < 4; ++nt)
                    mma_tf32(acc[mt][nt], aF[mt][0], aF[mt][1], aF[mt][2], aF[mt][3],
                             bF[nt][0], bF[nt][1]);
        }
        if (kc < 7) {
            const int nxt = cur ^ 1;
#pragma unroll
            for (int it = 0; it < 2; ++it) {
                int kk = w_k0 + it * 8;
                float* e = &Ws[(nxt * 16 + kk) * WPAD + w_c4];
                e[0] = __uint_as_float(f2tf32(pw[it].x));
                e[1] = __uint_as_float(f2tf32(pw[it].y));
                e[2] = __uint_as_float(f2tf32(pw[it].z));
                e[3] = __uint_as_float(f2tf32(pw[it].w));
            }
            __syncthreads();
        }
    }

    // epilogue 2: C = relu(acc + b2) -> global
#pragma unroll
    for (int nt = 0; nt < 4; ++nt) {
        const int col = warp_n * 32 + nt * 8 + (c << 1);
        const float bx = __ldg(b2 + col);
        const float by = __ldg(b2 + col + 1);
#pragma unroll
        for (int mt = 0; mt < 4; ++mt) {
            const int row0 = rowBase + warp_m * 64 + mt * 16 + g;
            if (row0 < M) {
                float2 v;
                v.x = fmaxf(acc[mt][nt][0] + bx, 0.0f);
                v.y = fmaxf(acc[mt][nt][1] + by, 0.0f);
                *(float2*)(C + (long long)row0 * 128 + col) = v;
            }
            const int row1 = row0 + 8;
            if (row1 < M) {
                float2 v;
                v.x = fmaxf(acc[mt][nt][2] + bx, 0.0f);
                v.y = fmaxf(acc[mt][nt][3] + by, 0.0f);
                *(float2*)(C + (long long)row1 * 128 + col) = v;
            }
        }
    }
}

// ---------------------------------------------------------------------------
// out = log_softmax(H @ Wl + bl)
// ---------------------------------------------------------------------------
__global__ __launch_bounds__(256) void k_cls(int h_sel, const float* __restrict__ Wl,
                                             const float* __restrict__ bl,
                                             float* __restrict__ out, int M) {
    const float* H = bufsel(h_sel);
    __shared__ float sW[128 * 40];
    __shared__ float sb[40];
    __shared__ float srow[8][128];

    const int tid = threadIdx.x;
    for (int i = tid; i < 128 * 40; i += 256) sW[i] = Wl[i];
    if (tid < 40) sb[tid] = bl[tid];
    __syncthreads();

    const int warp = tid >> 5, lane = tid & 31;
    const long long r = (long long)blockIdx.x * 8 + warp;
    if (r >= M) return;

    ((float4*)srow[warp])[lane] = ((const float4*)(H + r * 128))[lane];
    __syncwarp();

    const int c0 = lane;
    const int c1 = lane + 32;
    float acc0 = sb[c0];
    float acc1 = (c1 < 40) ? sb[c1] : -1e30f;
#pragma unroll 4
    for (int f = 0; f < 128; ++f) {
        float hv = srow[warp][f];
        acc0 = fmaf(hv, sW[f * 40 + c0], acc0);
        if (c1 < 40) acc1 = fmaf(hv, sW[f * 40 + c1], acc1);
    }
    float mx = fmaxf(acc0, acc1);
#pragma unroll
    for (int o = 16; o; o >>= 1) mx = fmaxf(mx, __shfl_xor_sync(0xFFFFFFFFu, mx, o));
    float s = expf(acc0 - mx) + ((c1 < 40) ? expf(acc1 - mx) : 0.0f);
#pragma unroll
    for (int o = 16; o; o >>= 1) s += __shfl_xor_sync(0xFFFFFFFFu, s, o);
    float lse = mx + logf(s);
    out[r * 40 + c0] = acc0 - lse;
    if (c1 < 40) out[r * 40 + c1] = acc1 - lse;
}

// ---------------------------------------------------------------------------
extern "C" void kernel_launch(void* const* d_in, const int* in_sizes, int n_in,
                              void* d_out, int out_size) {
    const float* x   = (const float*)d_in[0];
    const void*  ei  = d_in[1];
    const float* ea  = (const float*)d_in[2];
    const float* eps1 = (const float*)d_in[3];
    const float* We1 = (const float*)d_in[4];
    const float* be1 = (const float*)d_in[5];
    const float* W11 = (const float*)d_in[6];
    const float* b11 = (const float*)d_in[7];
    const float* W12 = (const float*)d_in[8];
    const float* b12 = (const float*)d_in[9];
    const float* eps2 = (const float*)d_in[10];
    const float* We2 = (const float*)d_in[11];
    const float* be2 = (const float*)d_in[12];
    const float* W21 = (const float*)d_in[13];
    const float* b21 = (const float*)d_in[14];
    const float* W22 = (const float*)d_in[15];
    const float* b22 = (const float*)d_in[16];
    const float* Wl  = (const float*)d_in[17];
    const float* bl  = (const float*)d_in[18];
    float* out = (float*)d_out;

    const int N = in_sizes[0] / FDIM;
    const int E = in_sizes[2];

    const int gn = (N + 255) / 256;
    const int ge = (E + 255) / 256;
    const int nb = (N + 1023) / 1024;
    const int ga = (N + 7) / 8;
    const int gg = (N + 127) / 128;
    const int gc = (N + 7) / 8;

    const int mlp_smem = (2 * 128 * APAD + 2 * 16 * WPAD + 128 * TPAD) * 4;
    cudaFuncSetAttribute(k_mlp, cudaFuncAttributeMaxDynamicSharedMemorySize,
                         mlp_smem);

    // ---- CSR build (shared by both convs) ----
    k_detect<<<1, 32>>>((const long long*)ei, N);
    k_zero<<<gn, 256>>>(N);
    k_hist<<<ge, 256>>>(ei, E);
    k_scan1<<<nb, 1024>>>(N);
    k_scan2<<<1, 128>>>(nb);
    k_scan3<<<gn, 256>>>(N, E);
    k_scatter<<<ge, 256>>>(ei, ea, E);

    // ---- conv1: x (external) -> A -> B ----
    k_aggr<<<ga, 256>>>((const float4*)x, -1, 0, eps1,
                        (const float4*)We1, (const float4*)be1, N);
    k_mlp<<<gg, 256, mlp_smem>>>(0, W11, b11, W12, b12, 1, N);

    // ---- conv2: B -> A -> B ----
    k_aggr<<<ga, 256>>>(nullptr, 1, 0, eps2,
                        (const float4*)We2, (const float4*)be2, N);
    k_mlp<<<gg, 256, mlp_smem>>>(0, W21, b21, W22, b22, 1, N);

    // ---- classifier ----
    k_cls<<<gc, 256>>>(1, Wl, bl, out, N);
}